// round 7
// baseline (speedup 1.0000x reference)
#include <cuda_runtime.h>
#include <cstdint>

// MazeBrain: recurrent adaptive-LIF, T=1200, B=16, N=1024.
// One CTA per batch, 1024 threads: 4-way row-split sparse gather (32 warps,
// ~8 float4 loads each), smem partial reduction, 256 owner threads do the
// neuron update. Dual-parity monotonic spike rings, 2 barriers/step.

#define T_STEPS 1200
#define BATCH   16
#define NN      1024
#define WHIST   1000
#define TPB     1024
#define NCG     256      // column groups (4 cols each)

__global__ void __launch_bounds__(TPB, 1)
mazebrain_kernel(const float* __restrict__ Iext,   // [T,B,N]
                 const float* __restrict__ W,      // [N,N]
                 float* __restrict__ out)          // [2,T,B,N]: spikes, potentials
{
    const int b    = blockIdx.x;
    const int tid  = threadIdx.x;
    const int lane = tid & 31;
    const int rg   = tid >> 8;      // row group 0..3
    const int cg   = tid & 255;     // column group
    const int m0   = cg * 4;
    const bool owner = (rg == 0);

    __shared__ int    s_list[2][NN];   // per-parity spike rings
    __shared__ int    s_cnt[2];        // per-parity monotonic counters
    __shared__ float4 s_part[TPB];     // gather partials [rg*256 + cg]

    if (tid == 0) { s_cnt[0] = 0; s_cnt[1] = 0; }
    __syncthreads();

    // owner-only neuron state
    float v[4], adapt[4], thr[4], rsum[4];
    int   refr[4];
#pragma unroll
    for (int k = 0; k < 4; k++) {
        v[k] = -65.0f; adapt[k] = 0.0f; thr[k] = -55.0f; rsum[k] = 0.0f; refr[k] = 0;
    }
    int consumed[2] = {0, 0};

    float* __restrict__ spikes_out = out;
    float* __restrict__ pot_out    = out + (size_t)T_STEPS * BATCH * NN;
    const size_t stride = (size_t)BATCH * NN;
    const float* __restrict__ Wm = W + m0;

    size_t ob = (size_t)b * NN + m0;
    float4 Ie_next = owner ? __ldg((const float4*)(Iext + ob))
                           : make_float4(0.f, 0.f, 0.f, 0.f);
    float4 hist_next = make_float4(0.f, 0.f, 0.f, 0.f);

    for (int t = 0; t < T_STEPS; t++) {
        const int p = t & 1;        // append parity
        const int q = p ^ 1;        // consume parity
        const float4 Ie   = Ie_next;
        const float4 hist = hist_next;

        // ---- row-split sparse gather: rg-th quarter of the spike list
        const int e  = s_cnt[q];
        const int i0 = consumed[q];
        const int nT = e - i0;
        consumed[q] = e;
        const int* __restrict__ lst = s_list[q];

        const int n4  = nT >> 2;
        const int rem = nT & 3;
        int i = i0 + rg * n4 + min(rg, rem);
        int n = n4 + (rg < rem ? 1 : 0);

        float a0 = 0.f, a1 = 0.f, a2 = 0.f, a3 = 0.f;
        while (n >= 8) {
            int j[8];
#pragma unroll
            for (int k = 0; k < 8; k++) j[k] = lst[(i + k) & (NN - 1)];
            float4 r[8];
#pragma unroll
            for (int k = 0; k < 8; k++)
                r[k] = *(const float4*)(Wm + ((size_t)j[k] << 10));
#pragma unroll
            for (int k = 0; k < 8; k++) {
                a0 += r[k].x; a1 += r[k].y; a2 += r[k].z; a3 += r[k].w;
            }
            i += 8; n -= 8;
        }
        if (n >= 4) {
            int j[4];
#pragma unroll
            for (int k = 0; k < 4; k++) j[k] = lst[(i + k) & (NN - 1)];
            float4 r[4];
#pragma unroll
            for (int k = 0; k < 4; k++)
                r[k] = *(const float4*)(Wm + ((size_t)j[k] << 10));
#pragma unroll
            for (int k = 0; k < 4; k++) {
                a0 += r[k].x; a1 += r[k].y; a2 += r[k].z; a3 += r[k].w;
            }
            i += 4; n -= 4;
        }
        while (n > 0) {
            float4 r = *(const float4*)(Wm + ((size_t)lst[i & (NN - 1)] << 10));
            a0 += r.x; a1 += r.y; a2 += r.z; a3 += r.w;
            i++; n--;
        }
        s_part[tid] = make_float4(a0, a1, a2, a3);

        __syncthreads();   // barrier A: partials visible

        if (owner) {
            // ---- reduce 4 partials + Iext (fixed order => deterministic)
            float4 p0 = s_part[cg];
            float4 p1 = s_part[cg + 256];
            float4 p2 = s_part[cg + 512];
            float4 p3 = s_part[cg + 768];
            float Iin[4];
            Iin[0] = Ie.x + ((p0.x + p1.x) + (p2.x + p3.x));
            Iin[1] = Ie.y + ((p0.y + p1.y) + (p2.y + p3.y));
            Iin[2] = Ie.z + ((p0.z + p1.z) + (p2.z + p3.z));
            Iin[3] = Ie.w + ((p0.w + p1.w) + (p2.w + p3.w));

            // ---- neuron update (integrate -> fire/reset -> adapt -> homeo)
            float spk[4], vout[4];
            bool  fired[4];
#pragma unroll
            for (int k = 0; k < 4; k++) {
                bool  active = (refr[k] <= 0);
                float v_int  = 0.9f * (v[k] + 65.0f) - 65.0f + Iin[k] - adapt[k];
                float v1     = active ? v_int : v[k];
                int   r1     = active ? refr[k] : (refr[k] - 1);
                fired[k] = (v1 >= thr[k]);
                spk[k]  = fired[k] ? 1.0f : 0.0f;
                v[k]    = fired[k] ? -70.0f : v1;
                vout[k] = v[k];
                adapt[k] = (fired[k] ? (adapt[k] + 0.2f) : adapt[k]) * 0.95f;
                refr[k]  = fired[k] ? 5 : r1;
            }

            // ---- warp-aggregated append (warps 0-7): 1 atomic per warp
            uint32_t b0 = __ballot_sync(0xffffffffu, fired[0]);
            uint32_t b1 = __ballot_sync(0xffffffffu, fired[1]);
            uint32_t b2 = __ballot_sync(0xffffffffu, fired[2]);
            uint32_t b3 = __ballot_sync(0xffffffffu, fired[3]);
            const int c0 = __popc(b0), c1 = __popc(b1), c2 = __popc(b2);
            const int wtot = c0 + c1 + c2 + __popc(b3);
            if (wtot) {
                int base = 0;
                if (lane == 0) base = atomicAdd(&s_cnt[p], wtot);
                base = __shfl_sync(0xffffffffu, base, 0);
                const uint32_t lt = (1u << lane) - 1u;
                if (fired[0]) s_list[p][(base + __popc(b0 & lt)) & (NN - 1)] = m0;
                if (fired[1]) s_list[p][(base + c0 + __popc(b1 & lt)) & (NN - 1)] = m0 + 1;
                if (fired[2]) s_list[p][(base + c0 + c1 + __popc(b2 & lt)) & (NN - 1)] = m0 + 2;
                if (fired[3]) s_list[p][(base + wtot - __popc(b3) + __popc(b3 & lt)) & (NN - 1)] = m0 + 3;
            }

            // ---- outputs (spikes region doubles as the homeostatic history)
            *(float4*)(spikes_out + ob) = make_float4(spk[0], spk[1], spk[2], spk[3]);
            *(float4*)(pot_out    + ob) = make_float4(vout[0], vout[1], vout[2], vout[3]);

            // ---- homeostatic sliding-window rate
            rsum[0] += spk[0] - hist.x; rsum[1] += spk[1] - hist.y;
            rsum[2] += spk[2] - hist.z; rsum[3] += spk[3] - hist.w;
            if (t + 1 >= WHIST) {
#pragma unroll
                for (int k = 0; k < 4; k++) {
                    float ta = thr[k] + 0.001f * (rsum[k] * (1.0f / WHIST) - 0.01f);
                    thr[k] = fminf(fmaxf(ta, 0.1f), 5.0f);
                }
            }

            // ---- prefetch next step's inputs
            const size_t ob_next = ob + stride;
            if (t + 1 < T_STEPS) {
                Ie_next = __ldg((const float4*)(Iext + ob_next));
                hist_next = (t + 1 >= WHIST)
                          ? *(const float4*)(spikes_out + (ob_next - (size_t)WHIST * stride))
                          : make_float4(0.f, 0.f, 0.f, 0.f);
            }
        }
        ob += stride;

        __syncthreads();   // barrier B: append(t) visible before gather(t+1)
    }
}

extern "C" void kernel_launch(void* const* d_in, const int* in_sizes, int n_in,
                              void* d_out, int out_size)
{
    const float* input_current = (const float*)d_in[0];  // [T,B,N]
    const float* W_rec         = (const float*)d_in[1];  // [N,N]
    float* out                 = (float*)d_out;          // [2,T,B,N]
    (void)in_sizes; (void)n_in; (void)out_size;

    mazebrain_kernel<<<BATCH, TPB>>>(input_current, W_rec, out);
}

// round 8
// speedup vs baseline: 1.1615x; 1.1615x over previous
#include <cuda_runtime.h>
#include <cstdint>

// MazeBrain: recurrent adaptive-LIF, T=1200, B=16, N=1024.
// One CTA per batch. 512 threads x 2 cols. Dual-parity monotonic spike rings
// storing BYTE OFFSETS (j<<12), 16-deep float2 gather, ONE barrier per step.

#define T_STEPS 1200
#define BATCH   16
#define NN      1024
#define WHIST   1000
#define TPB     512     // thread owns neurons 2*tid, 2*tid+1

__global__ void __launch_bounds__(TPB, 1)
mazebrain_kernel(const float* __restrict__ Iext,   // [T,B,N]
                 const float* __restrict__ W,      // [N,N]
                 float* __restrict__ out)          // [2,T,B,N]: spikes, potentials
{
    const int b   = blockIdx.x;
    const int tid = threadIdx.x;
    const int m0  = tid * 2;

    __shared__ int s_list[2][NN];   // per-parity spike ring: entries are j*4096 (byte offset)
    __shared__ int s_cnt[2];        // per-parity monotonic counters

    if (tid == 0) { s_cnt[0] = 0; s_cnt[1] = 0; }
    __syncthreads();

    float v[2], adapt[2], thr[2], rsum[2];
    int   refr[2];
#pragma unroll
    for (int k = 0; k < 2; k++) {
        v[k] = -65.0f; adapt[k] = 0.0f; thr[k] = -55.0f; rsum[k] = 0.0f; refr[k] = 0;
    }
    int consumed[2] = {0, 0};

    float* __restrict__ spikes_out = out;
    float* __restrict__ pot_out    = out + (size_t)T_STEPS * BATCH * NN;
    const size_t stride = (size_t)BATCH * NN;
    const char* __restrict__ Wb = (const char*)(W + m0);   // row 0, this thread's cols

    size_t ob = (size_t)b * NN + m0;
    float2 Ie_next   = __ldg((const float2*)(Iext + ob));
    float2 hist_next = make_float2(0.f, 0.f);

    for (int t = 0; t < T_STEPS; t++) {
        const int p = t & 1;        // append parity
        const int q = p ^ 1;        // consume parity
        const float2 Ie   = Ie_next;
        const float2 hist = hist_next;

        // ---- sparse gather of previous step's spikes (entries = byte offsets)
        const int e = s_cnt[q];
        int i = consumed[q];
        int n = e - i;
        consumed[q] = e;
        const int* __restrict__ lst = s_list[q];

        float a0 = Ie.x, a1 = Ie.y;
        while (n >= 16) {
            int o[16];
#pragma unroll
            for (int k = 0; k < 16; k++) o[k] = lst[(i + k) & (NN - 1)];
            float2 r[16];
#pragma unroll
            for (int k = 0; k < 16; k++)
                r[k] = *(const float2*)(Wb + o[k]);
#pragma unroll
            for (int k = 0; k < 16; k++) { a0 += r[k].x; a1 += r[k].y; }
            i += 16; n -= 16;
        }
        if (n >= 8) {
            int o[8];
#pragma unroll
            for (int k = 0; k < 8; k++) o[k] = lst[(i + k) & (NN - 1)];
            float2 r[8];
#pragma unroll
            for (int k = 0; k < 8; k++)
                r[k] = *(const float2*)(Wb + o[k]);
#pragma unroll
            for (int k = 0; k < 8; k++) { a0 += r[k].x; a1 += r[k].y; }
            i += 8; n -= 8;
        }
        if (n >= 4) {
            int o[4];
#pragma unroll
            for (int k = 0; k < 4; k++) o[k] = lst[(i + k) & (NN - 1)];
            float2 r[4];
#pragma unroll
            for (int k = 0; k < 4; k++)
                r[k] = *(const float2*)(Wb + o[k]);
#pragma unroll
            for (int k = 0; k < 4; k++) { a0 += r[k].x; a1 += r[k].y; }
            i += 4; n -= 4;
        }
        while (n > 0) {
            float2 r = *(const float2*)(Wb + lst[i & (NN - 1)]);
            a0 += r.x; a1 += r.y;
            i++; n--;
        }
        float Iin[2] = {a0, a1};

        // ---- neuron update (integrate -> fire/reset -> adapt -> homeo)
        float spk[2], vout[2];
        bool  fired[2];
#pragma unroll
        for (int k = 0; k < 2; k++) {
            bool  active = (refr[k] <= 0);
            float v_int  = 0.9f * (v[k] + 65.0f) - 65.0f + Iin[k] - adapt[k];
            float v1     = active ? v_int : v[k];
            int   r1     = active ? refr[k] : (refr[k] - 1);
            fired[k] = (v1 >= thr[k]);
            spk[k]  = fired[k] ? 1.0f : 0.0f;
            v[k]    = fired[k] ? -70.0f : v1;
            vout[k] = v[k];
            adapt[k] = (fired[k] ? (adapt[k] + 0.2f) : adapt[k]) * 0.95f;
            refr[k]  = fired[k] ? 5 : r1;
        }

        // ---- distributed append (entries stored as byte offsets j*4096)
#pragma unroll
        for (int k = 0; k < 2; k++) {
            if (fired[k]) {
                int idx = atomicAdd(&s_cnt[p], 1);
                s_list[p][idx & (NN - 1)] = (m0 + k) << 12;
            }
        }

        // ---- outputs (spikes region doubles as the homeostatic history ring)
        *(float2*)(spikes_out + ob) = make_float2(spk[0], spk[1]);
        *(float2*)(pot_out    + ob) = make_float2(vout[0], vout[1]);

        // ---- homeostatic sliding-window rate
        rsum[0] += spk[0] - hist.x;
        rsum[1] += spk[1] - hist.y;
        if (t + 1 >= WHIST) {
#pragma unroll
            for (int k = 0; k < 2; k++) {
                float ta = thr[k] + 0.001f * (rsum[k] * (1.0f / WHIST) - 0.01f);
                thr[k] = fminf(fmaxf(ta, 0.1f), 5.0f);
            }
        }

        // ---- prefetch next step's inputs
        const size_t ob_next = ob + stride;
        if (t + 1 < T_STEPS) {
            Ie_next = __ldg((const float2*)(Iext + ob_next));
            hist_next = (t + 1 >= WHIST)
                      ? *(const float2*)(spikes_out + (ob_next - (size_t)WHIST * stride))
                      : make_float2(0.f, 0.f);
        }
        ob = ob_next;

        __syncthreads();   // orders append(t) before gather(t+1)
    }
}

extern "C" void kernel_launch(void* const* d_in, const int* in_sizes, int n_in,
                              void* d_out, int out_size)
{
    const float* input_current = (const float*)d_in[0];  // [T,B,N]
    const float* W_rec         = (const float*)d_in[1];  // [N,N]
    float* out                 = (float*)d_out;          // [2,T,B,N]
    (void)in_sizes; (void)n_in; (void)out_size;

    mazebrain_kernel<<<BATCH, TPB>>>(input_current, W_rec, out);
}